// round 2
// baseline (speedup 1.0000x reference)
#include <cuda_runtime.h>
#include <math.h>

// Shapes (fixed): N=64, T=300, V=25, C=64, K=3, F=64, I=16, d=T*I=4800
#define SCALE_D 0.014433756729740645f   // 1/sqrt(4800)

// Scratch (module-static device memory; no runtime allocation)
__device__ float g_Spart[30 * 3 * 64 * 625];   // [chunk][k][n][v*25+w] partial scores, 14.4MB
__device__ float g_Aad[3 * 64 * 625];          // A_adapt [k][n][v*25+w]

// ---------------------------------------------------------------------------
// Kernel 1: attention score partials.
// Grid (30 t-chunks, 64 n), 256 threads. Each block accumulates, over its 10
// t-values, S[k][v][w] += (XWq_k + bq)(XWk_k + bk)^T in registers, then writes
// its chunk's partial to g_Spart (full coverage, no atomics -> deterministic).
// ---------------------------------------------------------------------------
__global__ __launch_bounds__(256) void score_kernel(
    const float* __restrict__ x,
    const float* __restrict__ Wq, const float* __restrict__ bq,
    const float* __restrict__ Wk, const float* __restrict__ bk)
{
    extern __shared__ float sm[];
    float* Gs  = sm;            // [64][96] combined Wq|Wk, cols j<48 Q (k*16+i), j>=48 K
    float* bs  = Gs + 6144;     // [96] bq|bk
    float* Xs  = bs + 96;       // [2][25][64]
    float* Qs  = Xs + 3200;     // [2][25][48]  Q with bias
    float* Kts = Qs + 2400;     // [2][3][16][28] K transposed (i-major, w contiguous)

    const int tid = threadIdx.x;
    const int chunk = blockIdx.x;
    const int n = blockIdx.y;

    // Load combined embedding weights into smem
    for (int e = tid; e < 6144; e += 256) {
        int c = e / 96, j = e % 96;
        float v;
        if (j < 48)  v = Wq[(j >> 4) * 1024 + c * 16 + (j & 15)];
        else { int jj = j - 48; v = Wk[(jj >> 4) * 1024 + c * 16 + (jj & 15)]; }
        Gs[e] = v;
    }
    if (tid < 96) bs[tid] = (tid < 48) ? bq[tid] : bk[tid - 48];

    // Persistent score accumulators: up to 2 tasks per thread (273 tasks total)
    float acc[2][2][4];
#pragma unroll
    for (int a = 0; a < 2; a++)
#pragma unroll
        for (int b2 = 0; b2 < 2; b2++)
#pragma unroll
            for (int c2 = 0; c2 < 4; c2++) acc[a][b2][c2] = 0.f;

    const float* xn = x + (n * 300 + chunk * 10) * 1600;

    for (int step = 0; step < 5; ++step) {
        __syncthreads();
        {   // load 2 consecutive t tiles (contiguous 3200 floats)
            const float4* src = (const float4*)(xn + step * 3200);
            float4* dst = (float4*)Xs;
            for (int e = tid; e < 800; e += 256) dst[e] = src[e];
        }
        __syncthreads();

        // --- Q/K embedding GEMM: E = X * [Wq|Wk] + bias, 240 tasks ---
        if (tid < 240) {
            int t2 = tid / 120, r = tid % 120;
            int qk = r / 60,   r2 = r % 60;
            int rowg = r2 / 12, ic = r2 % 12;
            int kq = ic >> 2,  i4 = ic & 3;

            float a0[5], a1[5], a2[5], a3[5];
#pragma unroll
            for (int rr = 0; rr < 5; rr++) { a0[rr] = a1[rr] = a2[rr] = a3[rr] = 0.f; }

            const float* Xb = Xs + t2 * 1600 + rowg * 320;
            const float4* G4 = (const float4*)Gs;
            const int gcol = qk * 12 + kq * 4 + i4;
#pragma unroll 8
            for (int c = 0; c < 64; ++c) {
                float4 g = G4[c * 24 + gcol];
#pragma unroll
                for (int rr = 0; rr < 5; ++rr) {
                    float xv = Xb[rr * 64 + c];
                    a0[rr] += xv * g.x; a1[rr] += xv * g.y;
                    a2[rr] += xv * g.z; a3[rr] += xv * g.w;
                }
            }
            const int bb0 = qk * 48 + kq * 16 + i4 * 4;
            const float b0 = bs[bb0], b1 = bs[bb0 + 1], b2 = bs[bb0 + 2], b3 = bs[bb0 + 3];
            if (qk == 0) {
#pragma unroll
                for (int rr = 0; rr < 5; ++rr) {
                    int row = rowg * 5 + rr;
                    float4 o = make_float4(a0[rr] + b0, a1[rr] + b1, a2[rr] + b2, a3[rr] + b3);
                    *(float4*)(Qs + t2 * 1200 + row * 48 + kq * 16 + i4 * 4) = o;
                }
            } else {
#pragma unroll
                for (int rr = 0; rr < 5; ++rr) {
                    int row = rowg * 5 + rr;
                    float* kb = Kts + t2 * 1344 + kq * 448 + (i4 * 4) * 28 + row;
                    kb[0]  = a0[rr] + b0;
                    kb[28] = a1[rr] + b1;
                    kb[56] = a2[rr] + b2;
                    kb[84] = a3[rr] + b3;
                }
            }
        }
        __syncthreads();

        // --- Score accumulation: S[k][v][w] += Q.K^T over i=16, for 2 t's ---
#pragma unroll
        for (int ti = 0; ti < 2; ++ti) {
#pragma unroll
            for (int task = 0; task < 2; ++task) {
                int s = tid + task * 256;
                if (s < 273) {
                    int kq = s / 91, r = s % 91;
                    int w4 = r / 13, vp = r % 13;
                    int v0 = 2 * vp;
                    int v1 = (2 * vp + 1 < 25) ? (2 * vp + 1) : 24;  // clamped; discarded at store
                    const float* q0p = Qs + ti * 1200 + v0 * 48 + kq * 16;
                    const float* q1p = Qs + ti * 1200 + v1 * 48 + kq * 16;
                    const float4* kt = (const float4*)(Kts + ti * 1344 + kq * 448 + w4 * 4);
#pragma unroll
                    for (int i = 0; i < 16; ++i) {
                        float4 kv = kt[i * 7];
                        float q0 = q0p[i], q1 = q1p[i];
                        acc[task][0][0] += q0 * kv.x; acc[task][0][1] += q0 * kv.y;
                        acc[task][0][2] += q0 * kv.z; acc[task][0][3] += q0 * kv.w;
                        acc[task][1][0] += q1 * kv.x; acc[task][1][1] += q1 * kv.y;
                        acc[task][1][2] += q1 * kv.z; acc[task][1][3] += q1 * kv.w;
                    }
                }
            }
        }
    }

    // --- write chunk partials ---
#pragma unroll
    for (int task = 0; task < 2; ++task) {
        int s = tid + task * 256;
        if (s < 273) {
            int kq = s / 91, r = s % 91;
            int w4 = r / 13, vp = r % 13;
            float* base = g_Spart + ((chunk * 3 + kq) * 64 + n) * 625;
#pragma unroll
            for (int vv = 0; vv < 2; ++vv) {
                int v = 2 * vp + vv;
                if (v < 25) {
#pragma unroll
                    for (int j = 0; j < 4; ++j) {
                        int w = w4 * 4 + j;
                        if (w < 25) base[v * 25 + w] = acc[task][vv][j];
                    }
                }
            }
        }
    }
}

// ---------------------------------------------------------------------------
// Kernel 2: reduce chunk partials (deterministic order), softmax over w, add A.
// Grid 192 = (k*64+n), 128 threads.
// ---------------------------------------------------------------------------
__global__ __launch_bounds__(128) void softmax_kernel(const float* __restrict__ A)
{
    __shared__ float S[625];
    const int b = blockIdx.x;
    const int kq = b / 64, n = b % 64;
    const int tid = threadIdx.x;

    for (int e = tid; e < 625; e += 128) {
        float s = 0.f;
        int base = ((kq * 64) + n) * 625 + e;
#pragma unroll 6
        for (int ch = 0; ch < 30; ++ch) s += g_Spart[ch * 120000 + base];
        S[e] = s;
    }
    __syncthreads();

    if (tid < 25) {
        const int v = tid;
        float m = -1e30f;
#pragma unroll
        for (int w = 0; w < 25; ++w) {
            float z = S[v * 25 + w] * SCALE_D;
            m = fmaxf(m, z);
        }
        float p[25];
        float sum = 0.f;
#pragma unroll
        for (int w = 0; w < 25; ++w) {
            p[w] = expf(S[v * 25 + w] * SCALE_D - m);
            sum += p[w];
        }
        float inv = 1.f / sum;
        float* dst = g_Aad + ((kq * 64) + n) * 625 + v * 25;
        const float* Ab = A + kq * 625 + v * 25;
#pragma unroll
        for (int w = 0; w < 25; ++w) dst[w] = Ab[w] + p[w] * inv;
    }
}

// ---------------------------------------------------------------------------
// Kernel 3: main path. Grid (25 t-chunks of 12, 64 n), 256 threads.
// Per t: H = X*W (25x192) in smem, then Y[w][f] = ybias + sum_{k,v} A[k][v][w]*H[v][k*64+f].
// Bias of the 1x1 conv folded into ybias = sum_k b_k (x) colsum_k(A_adapt).
// ---------------------------------------------------------------------------
__global__ __launch_bounds__(256) void main_kernel(
    const float* __restrict__ x, const float* __restrict__ W,
    const float* __restrict__ b, float* __restrict__ y)
{
    extern __shared__ float sm[];
    float* Ws    = sm;             // [64][192] = 12288
    float* Xs    = Ws + 12288;     // [25][64]  = 1600
    float* Hs    = Xs + 1600;      // [25][192] = 4800
    float* ybias = Hs + 4800;      // [25][64]  = 1600
    float* As    = ybias + 1600;   // [3][25][25] = 1875
    float* csum  = As + 1875;      // [3][25] = 75

    const int tid = threadIdx.x;
    const int n = blockIdx.y;
    const int tc = blockIdx.x;

    {   // load W (contiguous) and A_adapt for this n
        const float4* src = (const float4*)W;
        float4* dst = (float4*)Ws;
        for (int e = tid; e < 3072; e += 256) dst[e] = src[e];
    }
    for (int e = tid; e < 1875; e += 256) {
        int k = e / 625, rem = e % 625;
        As[e] = g_Aad[(k * 64 + n) * 625 + rem];
    }
    __syncthreads();

    if (tid < 75) {
        int k = tid / 25, w = tid % 25;
        float s = 0.f;
#pragma unroll
        for (int v = 0; v < 25; ++v) s += As[k * 625 + v * 25 + w];
        csum[tid] = s;
    }
    __syncthreads();
    for (int e = tid; e < 1600; e += 256) {
        int w = e / 64, f = e % 64;
        ybias[e] = b[f] * csum[w] + b[64 + f] * csum[25 + w] + b[128 + f] * csum[50 + w];
    }

    const int col4 = tid % 48;      // H phase (tid < 240)
    const int rowg = tid / 48;
    const int f4 = tid % 16;        // Y phase
    const int wg = tid / 16;
    const int w0 = wg;
    const int w1v = wg + 16;
    const int w1 = (w1v < 25) ? w1v : 0;   // clamped; store guarded

    for (int tt = 0; tt < 12; ++tt) {
        const int t = tc * 12 + tt;
        __syncthreads();
        {   // load X tile (contiguous 1600 floats)
            const float4* src = (const float4*)(x + (n * 300 + t) * 1600);
            float4* dst = (float4*)Xs;
            for (int e = tid; e < 400; e += 256) dst[e] = src[e];
        }
        __syncthreads();

        // --- H = X * W : 25x192, 5 rows x float4 per thread ---
        if (tid < 240) {
            float a0[5], a1[5], a2[5], a3[5];
#pragma unroll
            for (int r = 0; r < 5; ++r) { a0[r] = a1[r] = a2[r] = a3[r] = 0.f; }
            const float* Xb = Xs + rowg * 320;
            const float4* W4 = (const float4*)Ws;
#pragma unroll 8
            for (int c = 0; c < 64; ++c) {
                float4 wv = W4[c * 48 + col4];
#pragma unroll
                for (int r = 0; r < 5; ++r) {
                    float xv = Xb[r * 64 + c];
                    a0[r] += xv * wv.x; a1[r] += xv * wv.y;
                    a2[r] += xv * wv.z; a3[r] += xv * wv.w;
                }
            }
            float4* H4 = (float4*)Hs;
#pragma unroll
            for (int r = 0; r < 5; ++r)
                H4[(rowg * 5 + r) * 48 + col4] = make_float4(a0[r], a1[r], a2[r], a3[r]);
        }
        __syncthreads();

        // --- Y[w][f] = ybias + sum_k sum_v A[k][v][w] * H[v][k*64+f] ---
        {
            const float4* H4 = (const float4*)Hs;
            const float4* yb4 = (const float4*)ybias;
            float4 s0 = yb4[w0 * 16 + f4];
            float4 s1 = yb4[w1 * 16 + f4];
#pragma unroll
            for (int k = 0; k < 3; ++k) {
                const float* Ab = As + k * 625;
                const int hcol = k * 16 + f4;
#pragma unroll
                for (int v = 0; v < 25; ++v) {
                    float4 h = H4[v * 48 + hcol];
                    float av0 = Ab[v * 25 + w0];
                    float av1 = Ab[v * 25 + w1];
                    s0.x += av0 * h.x; s0.y += av0 * h.y; s0.z += av0 * h.z; s0.w += av0 * h.w;
                    s1.x += av1 * h.x; s1.y += av1 * h.y; s1.z += av1 * h.z; s1.w += av1 * h.w;
                }
            }
            float4* yout = (float4*)(y + (n * 300 + t) * 1600);
            yout[w0 * 16 + f4] = s0;
            if (w1v < 25) yout[w1v * 16 + f4] = s1;
        }
    }
}

// ---------------------------------------------------------------------------
extern "C" void kernel_launch(void* const* d_in, const int* in_sizes, int n_in,
                              void* d_out, int out_size)
{
    const float* x  = (const float*)d_in[0];
    const float* A  = (const float*)d_in[1];
    const float* W  = (const float*)d_in[2];
    const float* b  = (const float*)d_in[3];
    const float* Wq = (const float*)d_in[4];
    const float* bq = (const float*)d_in[5];
    const float* Wk = (const float*)d_in[6];
    const float* bk = (const float*)d_in[7];
    float* y = (float*)d_out;

    const int score_smem = 14528 * 4;   // 58112 B
    const int main_smem  = 22238 * 4;   // 88952 B
    cudaFuncSetAttribute(score_kernel, cudaFuncAttributeMaxDynamicSharedMemorySize, score_smem);
    cudaFuncSetAttribute(main_kernel,  cudaFuncAttributeMaxDynamicSharedMemorySize, main_smem);

    score_kernel<<<dim3(30, 64), 256, score_smem>>>(x, Wq, bq, Wk, bk);
    softmax_kernel<<<192, 128>>>(A);
    main_kernel<<<dim3(25, 64), 256, main_smem>>>(x, W, b, y);
}